// round 14
// baseline (speedup 1.0000x reference)
#include <cuda_runtime.h>
#include <math.h>
#include <float.h>

#define NUM_CLASSES 200
#define NUM_PROTO   10
#define EMBED_D     512
#define NQ          8192
#define ITERS       5
#define EPSF        0.01f
#define INV_EPS     100.0f
#define EPS_LOG     1e-8f
#define NCAP        192           // per-class row capacity (mean n_c ~41, sd 6.4)
#define SROW        12            // padded S row stride (16B-aligned)
#define FULLM       0xffffffffu

// per-half barriers: ids 1,2 = 512-thread half-sync; ids 3,4 = 320-thread Sinkhorn
#define HBAR(h) asm volatile("bar.sync %0, 512;" :: "r"(1 + (h)) : "memory")
#define B320(h) asm volatile("bar.sync %0, 320;" :: "r"(3 + (h)) : "memory")

// ---- dynamic smem layout (per half; byte offsets, 16B-aligned) -----------------
#define OFF_SP     0                                  // float [10*512]  20480 B
#define OFF_SSS    (OFF_SP   + NUM_PROTO*EMBED_D*4)   // float [192*12]   9216 B
#define OFF_SSV    (OFF_SSS  + NCAP*SROW*4)
#define OFF_SSI    (OFF_SSV  + NCAP*4)
#define OFF_SIDX   (OFF_SSI  + NCAP*4)
#define OFF_CMASK  (OFF_SIDX + NCAP*4)                // uint [256]
#define OFF_CPRE   (OFF_CMASK+ 256*4)                 // int  [256]
#define OFF_WSUM   (OFF_CPRE + 256*4)                 // int  [8]
#define OFF_SU     (OFF_WSUM + 8*4)                   // float[10]+pad
#define OFF_RED    (OFF_SU   + 48)                    // float[160]
#define OFF_SINV   (OFF_RED  + 160*4)                 // float[10]+pad
#define OFF_SN     (OFF_SINV + 48)                    // int s_n, s_lt
#define HALF_BYTES (OFF_SN + 16)                      // = 34832
#define SMEM_TOTAL (2 * HALF_BYTES)                   // = 69664 (< 228 KB)

// ---- fallback scratch (only if a class exceeds NCAP rows; statistically unreachable)
__device__ int   g_fidx[NQ];
__device__ float g_Sf[NQ * SROW];
__device__ float g_vf[NQ];
__device__ float g_if[NQ];

typedef unsigned long long ull;

__device__ __forceinline__ float dot4(float4 a, float4 b) {
    return a.x * b.x + a.y * b.y + a.z * b.z + a.w * b.w;
}
__device__ __forceinline__ float warp_sum(float v) {
    #pragma unroll
    for (int o = 16; o; o >>= 1) v += __shfl_xor_sync(FULLM, v, o);
    return v;
}
__device__ __forceinline__ float warp_max(float v) {
    #pragma unroll
    for (int o = 16; o; o >>= 1) v = fmaxf(v, __shfl_xor_sync(FULLM, v, o));
    return v;
}
// paired reduce: after pair_seed + 4-level butterfly, EVEN lanes hold sum(a),
// ODD lanes hold sum(b)
__device__ __forceinline__ float pair_seed(float a, float b, int lane) {
    float x = (lane & 1) ? a : b;
    x = __shfl_xor_sync(FULLM, x, 1);
    return ((lane & 1) ? b : a) + x;
}
__device__ __forceinline__ float pair_reduce(float a, float b, int lane) {
    float cr = pair_seed(a, b, lane);
    #pragma unroll
    for (int o = 2; o < 32; o <<= 1) cr += __shfl_xor_sync(FULLM, cr, o);
    return cr;
}
// ---- packed f32x2 helpers (sm_100+) --------------------------------------------
__device__ __forceinline__ ull pack2(float x) {
    ull r; asm("mov.b64 %0, {%1,%1};" : "=l"(r) : "f"(x)); return r;
}
__device__ __forceinline__ ull fma2(ull a, ull b, ull c) {
    ull d; asm("fma.rn.f32x2 %0, %1, %2, %3;" : "=l"(d) : "l"(a), "l"(b), "l"(c));
    return d;
}
__device__ __forceinline__ void unpack2(ull p, float& lo, float& hi) {
    asm("mov.b64 {%0,%1}, %2;" : "=f"(lo), "=f"(hi) : "l"(p));
}

// ---------------- per-class body (one 512-thread half) --------------------------
template<bool SM>
__device__ __forceinline__ void class_body(
    int c, int n_c, int half, int ltid,
    const float* __restrict__ tokens,
    float* __restrict__ out,
    const float* sp, const int* IDX,
    float* S, float* V, float* IV,
    float* su, float* red, float* sinv)
{
    int wid = ltid >> 5, lane = ltid & 31;

    // --- L2 prefetch: fire-and-forget the whole class's token rows NOW ---------
    // 16 x 128B lines per 2KB row; entire token array fits in L2 (16.8MB < 126MB).
    for (int k = ltid; k < (n_c << 4); k += 512) {
        const char* p = (const char*)(tokens + (size_t)IDX[k >> 4] * EMBED_D)
                      + ((k & 15) << 7);
        asm volatile("prefetch.global.L2 [%0];" :: "l"(p));
    }

    for (int i = ltid; i < n_c; i += 512) V[i] = 0.0f;
    HBAR(half);

    // --- phase A: TWO rows per warp iteration; proto reads shared, paired reduce --
    for (int i0 = 2 * wid; i0 < n_c; i0 += 32) {
        int i1 = i0 + 1;
        bool has2 = (i1 < n_c);                    // warp-uniform
        int n0 = IDX[i0];
        int n1 = IDX[has2 ? i1 : i0];
        const float4* ta = (const float4*)(tokens + (size_t)n0 * EMBED_D);
        const float4* tb = (const float4*)(tokens + (size_t)n1 * EMBED_D);
        float4 t0 = ta[lane], t1 = ta[lane + 32], t2 = ta[lane + 64], t3 = ta[lane + 96];
        float4 u0 = tb[lane], u1 = tb[lane + 32], u2 = tb[lane + 64], u3 = tb[lane + 96];
        float ss0 = dot4(t0, t0) + dot4(t1, t1) + dot4(t2, t2) + dot4(t3, t3);
        float ss1 = dot4(u0, u0) + dot4(u1, u1) + dot4(u2, u2) + dot4(u3, u3);
        float ssp = pair_reduce(ss0, ss1, lane);   // even: row0, odd: row1
        float inv = rsqrtf(ssp);
        if (lane == 0) IV[i0] = inv;
        else if (lane == 1 && has2) IV[i1] = inv;
        #pragma unroll
        for (int j = 0; j < NUM_PROTO; j++) {
            const float4* pp = (const float4*)(sp + j * EMBED_D);
            float4 p0 = pp[lane], p1 = pp[lane + 32], p2 = pp[lane + 64], p3 = pp[lane + 96];
            float d0 = dot4(t0, p0) + dot4(t1, p1) + dot4(t2, p2) + dot4(t3, p3);
            float d1 = dot4(u0, p0) + dot4(u1, p1) + dot4(u2, p2) + dot4(u3, p3);
            float dp = pair_reduce(d0, d1, lane);  // even: row0, odd: row1
            if (lane == 0) S[i0 * SROW + j] = dp * inv;
            else if (lane == 1 && has2) S[i1 * SROW + j] = dp * inv;
        }
    }
    HBAR(half);

    // --- phase B: 5 Sinkhorn iterations on warps 0-9 of this half ---
    if (wid < NUM_PROTO) {
        const float log_a = __logf(1.0f / (float)NUM_PROTO + EPS_LOG);
        const float log_b = __logf(1.0f / (float)n_c + EPS_LOG);
        for (int it = 0; it < ITERS; it++) {
            int j = wid;                       // u: warp j, two-pass max -> sum LSE
            float m = -FLT_MAX;
            for (int i = lane; i < n_c; i += 32)
                m = fmaxf(m, S[i * SROW + j] + V[i]);
            m = warp_max(m);
            float s = 0.0f;
            for (int i = lane; i < n_c; i += 32)
                s += __expf((S[i * SROW + j] + V[i] - m) * INV_EPS);
            s = warp_sum(s);
            if (lane == 0) su[j] = EPSF * log_a - m - EPSF * __logf(s);
            B320(half);
            for (int i = ltid; i < n_c; i += 320) {   // v: thread per row (320 thr)
                const float4 s0 = *(const float4*)(S + i * SROW);
                const float4 s1 = *(const float4*)(S + i * SROW + 4);
                const float2 s2 = *(const float2*)(S + i * SROW + 8);
                float b[NUM_PROTO] = {
                    s0.x + su[0], s0.y + su[1], s0.z + su[2], s0.w + su[3],
                    s1.x + su[4], s1.y + su[5], s1.z + su[6], s1.w + su[7],
                    s2.x + su[8], s2.y + su[9] };
                float mm = b[0];
                #pragma unroll
                for (int j2 = 1; j2 < NUM_PROTO; j2++) mm = fmaxf(mm, b[j2]);
                float ss = 0.0f;
                #pragma unroll
                for (int j2 = 0; j2 < NUM_PROTO; j2++) ss += __expf((b[j2] - mm) * INV_EPS);
                V[i] = EPSF * log_b - mm - EPSF * __logf(ss);
            }
            B320(half);
        }
    }
    HBAR(half);   // warps 10-15 rejoin; Sinkhorn results visible

    // --- phase C: column-normalized transport weights * inv-norm, in place ---
    for (int i = ltid; i < n_c; i += 512) {
        float vv = V[i];
        const float4 s0 = *(const float4*)(S + i * SROW);
        const float4 s1 = *(const float4*)(S + i * SROW + 4);
        const float2 s2 = *(const float2*)(S + i * SROW + 8);
        float w[NUM_PROTO] = {
            __expf((s0.x + su[0] + vv) * INV_EPS), __expf((s0.y + su[1] + vv) * INV_EPS),
            __expf((s0.z + su[2] + vv) * INV_EPS), __expf((s0.w + su[3] + vv) * INV_EPS),
            __expf((s1.x + su[4] + vv) * INV_EPS), __expf((s1.y + su[5] + vv) * INV_EPS),
            __expf((s1.z + su[6] + vv) * INV_EPS), __expf((s1.w + su[7] + vv) * INV_EPS),
            __expf((s2.x + su[8] + vv) * INV_EPS), __expf((s2.y + su[9] + vv) * INV_EPS) };
        float cs = 0.0f;
        #pragma unroll
        for (int j = 0; j < NUM_PROTO; j++) cs += w[j];
        float sc = IV[i] / cs;       // fold 1/||tok|| so phase D uses raw tokens
        *(float4*)(S + i * SROW)     = make_float4(w[0]*sc, w[1]*sc, w[2]*sc, w[3]*sc);
        *(float4*)(S + i * SROW + 4) = make_float4(w[4]*sc, w[5]*sc, w[6]*sc, w[7]*sc);
        *(float2*)(S + i * SROW + 8) = make_float2(w[8]*sc, w[9]*sc);
    }
    HBAR(half);

    // --- phase D: packed f32x2 accumulation (thread owns dim d) ---
    int d = ltid;
    ull acc2[5];
    #pragma unroll
    for (int h = 0; h < 5; h++) acc2[h] = 0ULL;

    #define DROW(ii, tv) {                                          \
        const ulonglong2 A = *(const ulonglong2*)(S + (ii) * SROW); \
        const ulonglong2 B = *(const ulonglong2*)(S + (ii) * SROW + 4); \
        const ull C = *(const ull*)(S + (ii) * SROW + 8);           \
        ull tt = pack2(tv);                                         \
        acc2[0] = fma2(A.x, tt, acc2[0]);                           \
        acc2[1] = fma2(A.y, tt, acc2[1]);                           \
        acc2[2] = fma2(B.x, tt, acc2[2]);                           \
        acc2[3] = fma2(B.y, tt, acc2[3]);                           \
        acc2[4] = fma2(C,   tt, acc2[4]); }

    int i = 0;
    for (; i + 4 <= n_c; i += 4) {               // 4 L1-warm loads in flight
        float t0 = __ldg(tokens + (size_t)IDX[i]     * EMBED_D + d);
        float t1 = __ldg(tokens + (size_t)IDX[i + 1] * EMBED_D + d);
        float t2 = __ldg(tokens + (size_t)IDX[i + 2] * EMBED_D + d);
        float t3 = __ldg(tokens + (size_t)IDX[i + 3] * EMBED_D + d);
        DROW(i,     t0); DROW(i + 1, t1);
        DROW(i + 2, t2); DROW(i + 3, t3);
    }
    for (; i < n_c; i++) {
        float t0 = __ldg(tokens + (size_t)IDX[i] * EMBED_D + d);
        DROW(i, t0);
    }
    #undef DROW
    float acc[NUM_PROTO];
    #pragma unroll
    for (int h = 0; h < 5; h++) unpack2(acc2[h], acc[2*h], acc[2*h+1]);

    // --- phase E: momentum blend + batched per-row l2norm + writeout ---
    float r[NUM_PROTO];
    #pragma unroll
    for (int j = 0; j < NUM_PROTO; j++) {
        r[j] = 0.98f * sp[j * EMBED_D + d] + 0.02f * acc[j];
        float x = warp_sum(r[j] * r[j]);
        if (lane == 0) red[wid * NUM_PROTO + j] = x;
    }
    HBAR(half);
    if (wid < NUM_PROTO) {
        int j = wid;
        float y = (lane < 16) ? red[lane * NUM_PROTO + j] : 0.0f;
        y = warp_sum(y);
        if (lane == 0) sinv[j] = rsqrtf(y);
    }
    HBAR(half);
    #pragma unroll
    for (int j = 0; j < NUM_PROTO; j++)
        out[(size_t)(c * NUM_PROTO + j) * EMBED_D + d] = r[j] * sinv[j];
}

// ---------------- fused kernel: 2 classes per block, shared label scan ----------
__global__ void __launch_bounds__(1024, 1)
k_main(const float* __restrict__ tokens,
       const void*  __restrict__ labels_raw,
       const float* __restrict__ protos,
       float* __restrict__ out) {
    extern __shared__ __align__(16) char dyn[];

    int tid  = threadIdx.x;
    int half = tid >> 9;
    int ltid = tid & 511;
    int wid  = ltid >> 5, lane = ltid & 31;
    int fw   = tid >> 5;                       // full-block warp id 0..31
    int c0   = blockIdx.x * 2, c1 = c0 + 1;
    int c    = c0 + half;

    char* hb  = dyn + half * HALF_BYTES;
    float*    sp    = (float*)(hb + OFF_SP);
    float*    ssS   = (float*)(hb + OFF_SSS);
    float*    ssV   = (float*)(hb + OFF_SSV);
    float*    ssI   = (float*)(hb + OFF_SSI);
    int*      sidx  = (int*)  (hb + OFF_SIDX);
    unsigned* cmask = (unsigned*)(hb + OFF_CMASK);
    int*      cpre  = (int*)  (hb + OFF_CPRE);
    int*      wsum  = (int*)  (hb + OFF_WSUM);
    float*    su    = (float*)(hb + OFF_SU);
    float*    red   = (float*)(hb + OFF_RED);
    float*    sinv  = (float*)(hb + OFF_SINV);
    int*      s_n   = (int*)  (hb + OFF_SN);
    int*      s_lt  = s_n + 1;
    unsigned* cm0   = (unsigned*)(dyn + OFF_CMASK);
    unsigned* cm1   = (unsigned*)(dyn + HALF_BYTES + OFF_CMASK);
    int*      lt0   = (int*)(dyn + OFF_SN) + 1;
    int*      lt1   = (int*)(dyn + HALF_BYTES + OFF_SN) + 1;

    // stage this half's prototypes (DRAM loads in flight during label scan)
    {
        const float4* pg = (const float4*)(protos + (size_t)c * NUM_PROTO * EMBED_D);
        float4* ps = (float4*)sp;
        for (int i = ltid; i < NUM_PROTO * EMBED_D / 4; i += 512) ps[i] = pg[i];
    }
    if (ltid == 0) *s_lt = 0;

    // per-warp label dtype detection (uniform branch, hoisted out of load loops)
    const long long* l64 = (const long long*)labels_raw;
    bool is64;
    {
        long long v = l64[lane];
        unsigned bal = __ballot_sync(FULLM, v >= 0 && v < NUM_CLASSES);
        is64 = (__popc(bal) >= 16);
    }
    __syncthreads();   // s_lt init visible block-wide before shared scan

    // --- shared pass 1: all 32 warps scan labels ONCE, masks for both classes ---
    const int4* l4 = (const int4*)labels_raw;
    int ltl0 = 0, ltl1 = 0;
    if (!is64) {
        #pragma unroll
        for (int k = 0; k < 2; k++) {            // 2 int4 per thread = 8192 labels
            int4 v = l4[tid + 1024 * k];
            unsigned a0 = __ballot_sync(FULLM, v.x == c0);
            unsigned a1 = __ballot_sync(FULLM, v.y == c0);
            unsigned a2 = __ballot_sync(FULLM, v.z == c0);
            unsigned a3 = __ballot_sync(FULLM, v.w == c0);
            unsigned b0 = __ballot_sync(FULLM, v.x == c1);
            unsigned b1 = __ballot_sync(FULLM, v.y == c1);
            unsigned b2 = __ballot_sync(FULLM, v.z == c1);
            unsigned b3 = __ballot_sync(FULLM, v.w == c1);
            unsigned p0 = __ballot_sync(FULLM, v.x < c0);
            unsigned p1 = __ballot_sync(FULLM, v.y < c0);
            unsigned p2 = __ballot_sync(FULLM, v.z < c0);
            unsigned p3 = __ballot_sync(FULLM, v.w < c0);
            unsigned q0 = __ballot_sync(FULLM, v.x < c1);
            unsigned q1 = __ballot_sync(FULLM, v.y < c1);
            unsigned q2 = __ballot_sync(FULLM, v.z < c1);
            unsigned q3 = __ballot_sync(FULLM, v.w < c1);
            if ((tid & 31) == 0) {
                int mb = (k * 32 + fw) * 4;
                cm0[mb] = a0; cm0[mb+1] = a1; cm0[mb+2] = a2; cm0[mb+3] = a3;
                cm1[mb] = b0; cm1[mb+1] = b1; cm1[mb+2] = b2; cm1[mb+3] = b3;
                ltl0 += __popc(p0) + __popc(p1) + __popc(p2) + __popc(p3);
                ltl1 += __popc(q0) + __popc(q1) + __popc(q2) + __popc(q3);
            }
        }
    } else {
        #pragma unroll
        for (int k = 0; k < 4; k++) {            // int4 = 2 int64 labels (.x, .z)
            int4 v = l4[tid + 1024 * k];
            unsigned a0 = __ballot_sync(FULLM, v.x == c0);
            unsigned a1 = __ballot_sync(FULLM, v.z == c0);
            unsigned b0 = __ballot_sync(FULLM, v.x == c1);
            unsigned b1 = __ballot_sync(FULLM, v.z == c1);
            unsigned p0 = __ballot_sync(FULLM, v.x < c0);
            unsigned p1 = __ballot_sync(FULLM, v.z < c0);
            unsigned q0 = __ballot_sync(FULLM, v.x < c1);
            unsigned q1 = __ballot_sync(FULLM, v.z < c1);
            if ((tid & 31) == 0) {
                int mb = (k * 32 + fw) * 2;
                cm0[mb] = a0; cm0[mb+1] = a1;
                cm1[mb] = b0; cm1[mb+1] = b1;
                ltl0 += __popc(p0) + __popc(p1);
                ltl1 += __popc(q0) + __popc(q1);
            }
        }
    }
    if ((tid & 31) == 0) {
        if (ltl0) atomicAdd(lt0, ltl0);          // int: deterministic
        if (ltl1) atomicAdd(lt1, ltl1);
    }
    __syncthreads();   // masks + lt visible; halves independent from here on

    // --- two-level exclusive prefix over 256 mask popcounts (per half) ---
    if (wid < 8) {
        int v = __popc(cmask[wid * 32 + lane]);
        int inc = v;
        #pragma unroll
        for (int o = 1; o < 32; o <<= 1) {
            int t = __shfl_up_sync(FULLM, inc, o);
            if (lane >= o) inc += t;
        }
        cpre[wid * 32 + lane] = inc - v;
        if (lane == 31) wsum[wid] = inc;
    }
    HBAR(half);
    if (wid == 0 && lane < 8) {
        int v = wsum[lane];
        int inc = v;
        #pragma unroll
        for (int o = 1; o < 8; o <<= 1) {
            int t = __shfl_up_sync(0xffu, inc, o);
            if (lane >= o) inc += t;
        }
        wsum[lane] = inc - v;
        if (lane == 7) *s_n = inc;
    }
    HBAR(half);

    int n_c = *s_n;
    if (n_c == 0) {   // out = l2norm(0.98*proto) = proto (unit-norm input)
        #pragma unroll
        for (int j = 0; j < NUM_PROTO; j++)
            out[(size_t)(c * NUM_PROTO + j) * EMBED_D + ltid] = sp[j * EMBED_D + ltid];
        return;
    }
    bool sm  = (n_c <= NCAP);
    int  off = *s_lt;
    int* dst = sm ? sidx : (g_fidx + off);

    // --- pass 2: replay cached masks; thread per sub-chunk, no label reloads ---
    if (ltid < 256) {
        unsigned m = cmask[ltid];
        if (m) {
            int pos = wsum[ltid >> 5] + cpre[ltid];
            int base;
            int mult = is64 ? 2 : 4;
            if (!is64) {
                int k = ltid >> 7, w = (ltid >> 2) & 31, cc = ltid & 3;
                base = 4 * (32 * w + 1024 * k) + cc;
            } else {
                int k = ltid >> 6, w = (ltid >> 1) & 31, cc = ltid & 1;
                base = 2 * (32 * w + 1024 * k) + cc;
            }
            while (m) {
                int l = __ffs(m) - 1; m &= m - 1;
                dst[pos++] = base + mult * l;
            }
        }
    }
    HBAR(half);

    if (sm) {
        class_body<true >(c, n_c, half, ltid, tokens, out, sp, sidx,
                          ssS, ssV, ssI, su, red, sinv);
    } else {  // statistically unreachable; correct fallback via global scratch
        class_body<false>(c, n_c, half, ltid, tokens, out, sp, g_fidx + off,
                          g_Sf + (size_t)off * SROW, g_vf + off, g_if + off,
                          su, red, sinv);
    }
}

// -------------------------------- launch ---------------------------------------
extern "C" void kernel_launch(void* const* d_in, const int* in_sizes, int n_in,
                              void* d_out, int out_size) {
    const float* tokens = (const float*)d_in[0];
    const void*  labels = d_in[1];
    const float* protos = (const float*)d_in[2];
    float* out = (float*)d_out;

    cudaFuncSetAttribute(k_main, cudaFuncAttributeMaxDynamicSharedMemorySize,
                         SMEM_TOTAL);
    k_main<<<NUM_CLASSES / 2, 1024, SMEM_TOTAL>>>(tokens, labels, protos, out);
}

// round 15
// speedup vs baseline: 1.0534x; 1.0534x over previous
#include <cuda_runtime.h>
#include <math.h>
#include <float.h>

#define NUM_CLASSES 200
#define NUM_PROTO   10
#define EMBED_D     512
#define NQ          8192
#define ITERS       5
#define EPSF        0.01f
#define INV_EPS     100.0f
#define EPS_LOG     1e-8f
#define NCAP        192           // per-class row capacity (mean n_c ~41, sd 6.4)
#define SROW        12            // padded S row stride (16B-aligned)
#define FULLM       0xffffffffu

// per-half barriers: ids 1,2 = 512-thread half-sync; ids 3,4 = 320-thread Sinkhorn
#define HBAR(h) asm volatile("bar.sync %0, 512;" :: "r"(1 + (h)) : "memory")
#define B320(h) asm volatile("bar.sync %0, 320;" :: "r"(3 + (h)) : "memory")

// ---- dynamic smem layout (per half; byte offsets, 16B-aligned) -----------------
#define OFF_SP     0                                  // float [10*512]  20480 B
#define OFF_SSS    (OFF_SP   + NUM_PROTO*EMBED_D*4)   // float [192*12]   9216 B
#define OFF_SSV    (OFF_SSS  + NCAP*SROW*4)
#define OFF_SSI    (OFF_SSV  + NCAP*4)
#define OFF_SIDX   (OFF_SSI  + NCAP*4)
#define OFF_CMASK  (OFF_SIDX + NCAP*4)                // uint [256]
#define OFF_CPRE   (OFF_CMASK+ 256*4)                 // int  [256]
#define OFF_WSUM   (OFF_CPRE + 256*4)                 // int  [8]
#define OFF_SU     (OFF_WSUM + 8*4)                   // float[10]+pad
#define OFF_RED    (OFF_SU   + 48)                    // float[160]
#define OFF_SINV   (OFF_RED  + 160*4)                 // float[10]+pad
#define OFF_SN     (OFF_SINV + 48)                    // int s_n, s_lt
#define HALF_BYTES (OFF_SN + 16)                      // = 34832
#define SMEM_TOTAL (2 * HALF_BYTES)                   // = 69664 (< 228 KB)

// ---- fallback scratch (only if a class exceeds NCAP rows; statistically unreachable)
__device__ int   g_fidx[NQ];
__device__ float g_Sf[NQ * SROW];
__device__ float g_vf[NQ];
__device__ float g_if[NQ];

typedef unsigned long long ull;

__device__ __forceinline__ float warp_sum(float v) {
    #pragma unroll
    for (int o = 16; o; o >>= 1) v += __shfl_xor_sync(FULLM, v, o);
    return v;
}
__device__ __forceinline__ float warp_max(float v) {
    #pragma unroll
    for (int o = 16; o; o >>= 1) v = fmaxf(v, __shfl_xor_sync(FULLM, v, o));
    return v;
}
// paired reduce: after pair_seed + 4-level butterfly, EVEN lanes hold sum(a),
// ODD lanes hold sum(b)
__device__ __forceinline__ float pair_seed(float a, float b, int lane) {
    float x = (lane & 1) ? a : b;
    x = __shfl_xor_sync(FULLM, x, 1);
    return ((lane & 1) ? b : a) + x;
}
__device__ __forceinline__ float pair_reduce(float a, float b, int lane) {
    float cr = pair_seed(a, b, lane);
    #pragma unroll
    for (int o = 2; o < 32; o <<= 1) cr += __shfl_xor_sync(FULLM, cr, o);
    return cr;
}
// ---- packed f32x2 helpers (sm_100+) --------------------------------------------
__device__ __forceinline__ ull pack2(float x) {
    ull r; asm("mov.b64 %0, {%1,%1};" : "=l"(r) : "f"(x)); return r;
}
__device__ __forceinline__ ull fma2(ull a, ull b, ull c) {
    ull d; asm("fma.rn.f32x2 %0, %1, %2, %3;" : "=l"(d) : "l"(a), "l"(b), "l"(c));
    return d;
}
__device__ __forceinline__ void unpack2(ull p, float& lo, float& hi) {
    asm("mov.b64 {%0,%1}, %2;" : "=f"(lo), "=f"(hi) : "l"(p));
}
__device__ __forceinline__ float hadd2(ull p) {
    float lo, hi; unpack2(p, lo, hi); return lo + hi;
}
// packed dot of one 16-float chunk pair set: acc += a*b elementwise (f32x2)
__device__ __forceinline__ ull dotu2(ulonglong2 a, ulonglong2 b, ull acc) {
    acc = fma2(a.x, b.x, acc);
    return fma2(a.y, b.y, acc);
}

// ---------------- per-class body (one 512-thread half) --------------------------
template<bool SM>
__device__ __forceinline__ void class_body(
    int c, int n_c, int half, int ltid,
    const float* __restrict__ tokens,
    float* __restrict__ out,
    const float* sp, const int* IDX,
    float* S, float* V, float* IV,
    float* su, float* red, float* sinv)
{
    int wid = ltid >> 5, lane = ltid & 31;

    for (int i = ltid; i < n_c; i += 512) V[i] = 0.0f;
    HBAR(half);

    // --- phase A: TWO rows per warp iteration; f32x2 dots; paired reduce ---------
    for (int i0 = 2 * wid; i0 < n_c; i0 += 32) {
        int i1 = i0 + 1;
        bool has2 = (i1 < n_c);                    // warp-uniform
        int n0 = IDX[i0];
        int n1 = IDX[has2 ? i1 : i0];
        const ulonglong2* ta = (const ulonglong2*)(tokens + (size_t)n0 * EMBED_D);
        const ulonglong2* tb = (const ulonglong2*)(tokens + (size_t)n1 * EMBED_D);
        ulonglong2 t0 = ta[lane], t1 = ta[lane + 32], t2 = ta[lane + 64], t3 = ta[lane + 96];
        ulonglong2 u0 = tb[lane], u1 = tb[lane + 32], u2 = tb[lane + 64], u3 = tb[lane + 96];
        ull sa = dotu2(t0, t0, 0ULL); sa = dotu2(t1, t1, sa);
        sa = dotu2(t2, t2, sa);       sa = dotu2(t3, t3, sa);
        ull sb = dotu2(u0, u0, 0ULL); sb = dotu2(u1, u1, sb);
        sb = dotu2(u2, u2, sb);       sb = dotu2(u3, u3, sb);
        float ssp = pair_reduce(hadd2(sa), hadd2(sb), lane);   // even: r0, odd: r1
        float inv = rsqrtf(ssp);
        if (lane == 0) IV[i0] = inv;
        else if (lane == 1 && has2) IV[i1] = inv;
        #pragma unroll
        for (int j = 0; j < NUM_PROTO; j++) {
            const ulonglong2* pp = (const ulonglong2*)(sp + j * EMBED_D);
            ulonglong2 p0 = pp[lane], p1 = pp[lane + 32], p2 = pp[lane + 64], p3 = pp[lane + 96];
            ull da = dotu2(t0, p0, 0ULL); da = dotu2(t1, p1, da);
            da = dotu2(t2, p2, da);       da = dotu2(t3, p3, da);
            ull db = dotu2(u0, p0, 0ULL); db = dotu2(u1, p1, db);
            db = dotu2(u2, p2, db);       db = dotu2(u3, p3, db);
            float dp = pair_reduce(hadd2(da), hadd2(db), lane);  // even: r0, odd: r1
            if (lane == 0) S[i0 * SROW + j] = dp * inv;
            else if (lane == 1 && has2) S[i1 * SROW + j] = dp * inv;
        }
    }
    HBAR(half);

    // --- phase B: 5 Sinkhorn iterations on warps 0-9 of this half ---
    if (wid < NUM_PROTO) {
        const float log_a = __logf(1.0f / (float)NUM_PROTO + EPS_LOG);
        const float log_b = __logf(1.0f / (float)n_c + EPS_LOG);
        for (int it = 0; it < ITERS; it++) {
            int j = wid;                       // u: warp j, two-pass max -> sum LSE
            float m = -FLT_MAX;
            for (int i = lane; i < n_c; i += 32)
                m = fmaxf(m, S[i * SROW + j] + V[i]);
            m = warp_max(m);
            float s = 0.0f;
            for (int i = lane; i < n_c; i += 32)
                s += __expf((S[i * SROW + j] + V[i] - m) * INV_EPS);
            s = warp_sum(s);
            if (lane == 0) su[j] = EPSF * log_a - m - EPSF * __logf(s);
            B320(half);
            for (int i = ltid; i < n_c; i += 320) {   // v: thread per row (320 thr)
                const float4 s0 = *(const float4*)(S + i * SROW);
                const float4 s1 = *(const float4*)(S + i * SROW + 4);
                const float2 s2 = *(const float2*)(S + i * SROW + 8);
                float b[NUM_PROTO] = {
                    s0.x + su[0], s0.y + su[1], s0.z + su[2], s0.w + su[3],
                    s1.x + su[4], s1.y + su[5], s1.z + su[6], s1.w + su[7],
                    s2.x + su[8], s2.y + su[9] };
                float mm = b[0];
                #pragma unroll
                for (int j2 = 1; j2 < NUM_PROTO; j2++) mm = fmaxf(mm, b[j2]);
                float ss = 0.0f;
                #pragma unroll
                for (int j2 = 0; j2 < NUM_PROTO; j2++) ss += __expf((b[j2] - mm) * INV_EPS);
                V[i] = EPSF * log_b - mm - EPSF * __logf(ss);
            }
            B320(half);
        }
    }
    HBAR(half);   // warps 10-15 rejoin; Sinkhorn results visible

    // --- phase C: column-normalized transport weights * inv-norm, in place ---
    for (int i = ltid; i < n_c; i += 512) {
        float vv = V[i];
        const float4 s0 = *(const float4*)(S + i * SROW);
        const float4 s1 = *(const float4*)(S + i * SROW + 4);
        const float2 s2 = *(const float2*)(S + i * SROW + 8);
        float w[NUM_PROTO] = {
            __expf((s0.x + su[0] + vv) * INV_EPS), __expf((s0.y + su[1] + vv) * INV_EPS),
            __expf((s0.z + su[2] + vv) * INV_EPS), __expf((s0.w + su[3] + vv) * INV_EPS),
            __expf((s1.x + su[4] + vv) * INV_EPS), __expf((s1.y + su[5] + vv) * INV_EPS),
            __expf((s1.z + su[6] + vv) * INV_EPS), __expf((s1.w + su[7] + vv) * INV_EPS),
            __expf((s2.x + su[8] + vv) * INV_EPS), __expf((s2.y + su[9] + vv) * INV_EPS) };
        float cs = 0.0f;
        #pragma unroll
        for (int j = 0; j < NUM_PROTO; j++) cs += w[j];
        float sc = IV[i] / cs;       // fold 1/||tok|| so phase D uses raw tokens
        *(float4*)(S + i * SROW)     = make_float4(w[0]*sc, w[1]*sc, w[2]*sc, w[3]*sc);
        *(float4*)(S + i * SROW + 4) = make_float4(w[4]*sc, w[5]*sc, w[6]*sc, w[7]*sc);
        *(float2*)(S + i * SROW + 8) = make_float2(w[8]*sc, w[9]*sc);
    }
    HBAR(half);

    // --- phase D: packed f32x2 accumulation (thread owns dim d) ---
    int d = ltid;
    ull acc2[5];
    #pragma unroll
    for (int h = 0; h < 5; h++) acc2[h] = 0ULL;

    #define DROW(ii, tv) {                                          \
        const ulonglong2 A = *(const ulonglong2*)(S + (ii) * SROW); \
        const ulonglong2 B = *(const ulonglong2*)(S + (ii) * SROW + 4); \
        const ull C = *(const ull*)(S + (ii) * SROW + 8);           \
        ull tt = pack2(tv);                                         \
        acc2[0] = fma2(A.x, tt, acc2[0]);                           \
        acc2[1] = fma2(A.y, tt, acc2[1]);                           \
        acc2[2] = fma2(B.x, tt, acc2[2]);                           \
        acc2[3] = fma2(B.y, tt, acc2[3]);                           \
        acc2[4] = fma2(C,   tt, acc2[4]); }

    int i = 0;
    for (; i + 4 <= n_c; i += 4) {               // 4 L1-warm loads in flight
        float t0 = __ldg(tokens + (size_t)IDX[i]     * EMBED_D + d);
        float t1 = __ldg(tokens + (size_t)IDX[i + 1] * EMBED_D + d);
        float t2 = __ldg(tokens + (size_t)IDX[i + 2] * EMBED_D + d);
        float t3 = __ldg(tokens + (size_t)IDX[i + 3] * EMBED_D + d);
        DROW(i,     t0); DROW(i + 1, t1);
        DROW(i + 2, t2); DROW(i + 3, t3);
    }
    for (; i < n_c; i++) {
        float t0 = __ldg(tokens + (size_t)IDX[i] * EMBED_D + d);
        DROW(i, t0);
    }
    #undef DROW
    float acc[NUM_PROTO];
    #pragma unroll
    for (int h = 0; h < 5; h++) unpack2(acc2[h], acc[2*h], acc[2*h+1]);

    // --- phase E: momentum blend + batched per-row l2norm + writeout ---
    float r[NUM_PROTO];
    #pragma unroll
    for (int j = 0; j < NUM_PROTO; j++) {
        r[j] = 0.98f * sp[j * EMBED_D + d] + 0.02f * acc[j];
        float x = warp_sum(r[j] * r[j]);
        if (lane == 0) red[wid * NUM_PROTO + j] = x;
    }
    HBAR(half);
    if (wid < NUM_PROTO) {
        int j = wid;
        float y = (lane < 16) ? red[lane * NUM_PROTO + j] : 0.0f;
        y = warp_sum(y);
        if (lane == 0) sinv[j] = rsqrtf(y);
    }
    HBAR(half);
    #pragma unroll
    for (int j = 0; j < NUM_PROTO; j++)
        out[(size_t)(c * NUM_PROTO + j) * EMBED_D + d] = r[j] * sinv[j];
}

// ---------------- fused kernel: 2 classes per block, shared label scan ----------
__global__ void __launch_bounds__(1024, 1)
k_main(const float* __restrict__ tokens,
       const void*  __restrict__ labels_raw,
       const float* __restrict__ protos,
       float* __restrict__ out) {
    extern __shared__ __align__(16) char dyn[];

    int tid  = threadIdx.x;
    int half = tid >> 9;
    int ltid = tid & 511;
    int wid  = ltid >> 5, lane = ltid & 31;
    int fw   = tid >> 5;                       // full-block warp id 0..31
    int c0   = blockIdx.x * 2, c1 = c0 + 1;
    int c    = c0 + half;

    char* hb  = dyn + half * HALF_BYTES;
    float*    sp    = (float*)(hb + OFF_SP);
    float*    ssS   = (float*)(hb + OFF_SSS);
    float*    ssV   = (float*)(hb + OFF_SSV);
    float*    ssI   = (float*)(hb + OFF_SSI);
    int*      sidx  = (int*)  (hb + OFF_SIDX);
    unsigned* cmask = (unsigned*)(hb + OFF_CMASK);
    int*      cpre  = (int*)  (hb + OFF_CPRE);
    int*      wsum  = (int*)  (hb + OFF_WSUM);
    float*    su    = (float*)(hb + OFF_SU);
    float*    red   = (float*)(hb + OFF_RED);
    float*    sinv  = (float*)(hb + OFF_SINV);
    int*      s_n   = (int*)  (hb + OFF_SN);
    int*      s_lt  = s_n + 1;
    unsigned* cm0   = (unsigned*)(dyn + OFF_CMASK);
    unsigned* cm1   = (unsigned*)(dyn + HALF_BYTES + OFF_CMASK);
    int*      lt0   = (int*)(dyn + OFF_SN) + 1;
    int*      lt1   = (int*)(dyn + HALF_BYTES + OFF_SN) + 1;

    // stage this half's prototypes (DRAM loads in flight during label scan)
    {
        const float4* pg = (const float4*)(protos + (size_t)c * NUM_PROTO * EMBED_D);
        float4* ps = (float4*)sp;
        for (int i = ltid; i < NUM_PROTO * EMBED_D / 4; i += 512) ps[i] = pg[i];
    }
    if (ltid == 0) *s_lt = 0;

    // per-warp label dtype detection (uniform branch, hoisted out of load loops)
    const long long* l64 = (const long long*)labels_raw;
    bool is64;
    {
        long long v = l64[lane];
        unsigned bal = __ballot_sync(FULLM, v >= 0 && v < NUM_CLASSES);
        is64 = (__popc(bal) >= 16);
    }
    __syncthreads();   // s_lt init visible block-wide before shared scan

    // --- shared pass 1: all 32 warps scan labels ONCE, masks for both classes ---
    const int4* l4 = (const int4*)labels_raw;
    int ltl0 = 0, ltl1 = 0;
    if (!is64) {
        #pragma unroll
        for (int k = 0; k < 2; k++) {            // 2 int4 per thread = 8192 labels
            int4 v = l4[tid + 1024 * k];
            unsigned a0 = __ballot_sync(FULLM, v.x == c0);
            unsigned a1 = __ballot_sync(FULLM, v.y == c0);
            unsigned a2 = __ballot_sync(FULLM, v.z == c0);
            unsigned a3 = __ballot_sync(FULLM, v.w == c0);
            unsigned b0 = __ballot_sync(FULLM, v.x == c1);
            unsigned b1 = __ballot_sync(FULLM, v.y == c1);
            unsigned b2 = __ballot_sync(FULLM, v.z == c1);
            unsigned b3 = __ballot_sync(FULLM, v.w == c1);
            unsigned p0 = __ballot_sync(FULLM, v.x < c0);
            unsigned p1 = __ballot_sync(FULLM, v.y < c0);
            unsigned p2 = __ballot_sync(FULLM, v.z < c0);
            unsigned p3 = __ballot_sync(FULLM, v.w < c0);
            unsigned q0 = __ballot_sync(FULLM, v.x < c1);
            unsigned q1 = __ballot_sync(FULLM, v.y < c1);
            unsigned q2 = __ballot_sync(FULLM, v.z < c1);
            unsigned q3 = __ballot_sync(FULLM, v.w < c1);
            if ((tid & 31) == 0) {
                int mb = (k * 32 + fw) * 4;
                cm0[mb] = a0; cm0[mb+1] = a1; cm0[mb+2] = a2; cm0[mb+3] = a3;
                cm1[mb] = b0; cm1[mb+1] = b1; cm1[mb+2] = b2; cm1[mb+3] = b3;
                ltl0 += __popc(p0) + __popc(p1) + __popc(p2) + __popc(p3);
                ltl1 += __popc(q0) + __popc(q1) + __popc(q2) + __popc(q3);
            }
        }
    } else {
        #pragma unroll
        for (int k = 0; k < 4; k++) {            // int4 = 2 int64 labels (.x, .z)
            int4 v = l4[tid + 1024 * k];
            unsigned a0 = __ballot_sync(FULLM, v.x == c0);
            unsigned a1 = __ballot_sync(FULLM, v.z == c0);
            unsigned b0 = __ballot_sync(FULLM, v.x == c1);
            unsigned b1 = __ballot_sync(FULLM, v.z == c1);
            unsigned p0 = __ballot_sync(FULLM, v.x < c0);
            unsigned p1 = __ballot_sync(FULLM, v.z < c0);
            unsigned q0 = __ballot_sync(FULLM, v.x < c1);
            unsigned q1 = __ballot_sync(FULLM, v.z < c1);
            if ((tid & 31) == 0) {
                int mb = (k * 32 + fw) * 2;
                cm0[mb] = a0; cm0[mb+1] = a1;
                cm1[mb] = b0; cm1[mb+1] = b1;
                ltl0 += __popc(p0) + __popc(p1);
                ltl1 += __popc(q0) + __popc(q1);
            }
        }
    }
    if ((tid & 31) == 0) {
        if (ltl0) atomicAdd(lt0, ltl0);          // int: deterministic
        if (ltl1) atomicAdd(lt1, ltl1);
    }
    __syncthreads();   // masks + lt visible; halves independent from here on

    // --- two-level exclusive prefix over 256 mask popcounts (per half) ---
    if (wid < 8) {
        int v = __popc(cmask[wid * 32 + lane]);
        int inc = v;
        #pragma unroll
        for (int o = 1; o < 32; o <<= 1) {
            int t = __shfl_up_sync(FULLM, inc, o);
            if (lane >= o) inc += t;
        }
        cpre[wid * 32 + lane] = inc - v;
        if (lane == 31) wsum[wid] = inc;
    }
    HBAR(half);
    if (wid == 0 && lane < 8) {
        int v = wsum[lane];
        int inc = v;
        #pragma unroll
        for (int o = 1; o < 8; o <<= 1) {
            int t = __shfl_up_sync(0xffu, inc, o);
            if (lane >= o) inc += t;
        }
        wsum[lane] = inc - v;
        if (lane == 7) *s_n = inc;
    }
    HBAR(half);

    int n_c = *s_n;
    if (n_c == 0) {   // out = l2norm(0.98*proto) = proto (unit-norm input)
        #pragma unroll
        for (int j = 0; j < NUM_PROTO; j++)
            out[(size_t)(c * NUM_PROTO + j) * EMBED_D + ltid] = sp[j * EMBED_D + ltid];
        return;
    }
    bool sm  = (n_c <= NCAP);
    int  off = *s_lt;
    int* dst = sm ? sidx : (g_fidx + off);

    // --- pass 2: replay cached masks; thread per sub-chunk, no label reloads ---
    if (ltid < 256) {
        unsigned m = cmask[ltid];
        if (m) {
            int pos = wsum[ltid >> 5] + cpre[ltid];
            int base;
            int mult = is64 ? 2 : 4;
            if (!is64) {
                int k = ltid >> 7, w = (ltid >> 2) & 31, cc = ltid & 3;
                base = 4 * (32 * w + 1024 * k) + cc;
            } else {
                int k = ltid >> 6, w = (ltid >> 1) & 31, cc = ltid & 1;
                base = 2 * (32 * w + 1024 * k) + cc;
            }
            while (m) {
                int l = __ffs(m) - 1; m &= m - 1;
                dst[pos++] = base + mult * l;
            }
        }
    }
    HBAR(half);

    if (sm) {
        class_body<true >(c, n_c, half, ltid, tokens, out, sp, sidx,
                          ssS, ssV, ssI, su, red, sinv);
    } else {  // statistically unreachable; correct fallback via global scratch
        class_body<false>(c, n_c, half, ltid, tokens, out, sp, g_fidx + off,
                          g_Sf + (size_t)off * SROW, g_vf + off, g_if + off,
                          su, red, sinv);
    }
}

// -------------------------------- launch ---------------------------------------
extern "C" void kernel_launch(void* const* d_in, const int* in_sizes, int n_in,
                              void* d_out, int out_size) {
    const float* tokens = (const float*)d_in[0];
    const void*  labels = d_in[1];
    const float* protos = (const float*)d_in[2];
    float* out = (float*)d_out;

    cudaFuncSetAttribute(k_main, cudaFuncAttributeMaxDynamicSharedMemorySize,
                         SMEM_TOTAL);
    k_main<<<NUM_CLASSES / 2, 1024, SMEM_TOTAL>>>(tokens, labels, protos, out);
}

// round 16
// speedup vs baseline: 1.0622x; 1.0083x over previous
#include <cuda_runtime.h>
#include <math.h>
#include <float.h>

#define NUM_CLASSES 200
#define NUM_PROTO   10
#define EMBED_D     512
#define NQ          8192
#define ITERS       5
#define EPSF        0.01f
#define INV_EPS     100.0f
#define EPS_LOG     1e-8f
#define NCAP        192           // per-class row capacity (mean n_c ~41, sd 6.4)
#define SROW        12            // padded S row stride (16B-aligned)
#define FULLM       0xffffffffu

// per-half barriers: ids 1,2 = 512-thread half-sync; ids 3,4 = 320-thread Sinkhorn
#define HBAR(h) asm volatile("bar.sync %0, 512;" :: "r"(1 + (h)) : "memory")
#define B320(h) asm volatile("bar.sync %0, 320;" :: "r"(3 + (h)) : "memory")

// ---- dynamic smem layout (per half; byte offsets, 16B-aligned) -----------------
#define OFF_SP     0                                  // float [10*512]  20480 B
#define OFF_SSS    (OFF_SP   + NUM_PROTO*EMBED_D*4)   // float [192*12]   9216 B
#define OFF_SSV    (OFF_SSS  + NCAP*SROW*4)
#define OFF_SSI    (OFF_SSV  + NCAP*4)
#define OFF_SIDX   (OFF_SSI  + NCAP*4)
#define OFF_CMASK  (OFF_SIDX + NCAP*4)                // uint [256]
#define OFF_CPRE   (OFF_CMASK+ 256*4)                 // int  [256]
#define OFF_WSUM   (OFF_CPRE + 256*4)                 // int  [8]
#define OFF_SU     (OFF_WSUM + 8*4)                   // float[10]+pad
#define OFF_RED    (OFF_SU   + 48)                    // float[160]
#define OFF_SINV   (OFF_RED  + 160*4)                 // float[10]+pad
#define OFF_SN     (OFF_SINV + 48)                    // int s_n, s_lt
#define HALF_BYTES (OFF_SN + 16)                      // = 34832
#define SMEM_TOTAL (2 * HALF_BYTES)                   // = 69664 (< 228 KB)

// ---- fallback scratch (only if a class exceeds NCAP rows; statistically unreachable)
__device__ int   g_fidx[NQ];
__device__ float g_Sf[NQ * SROW];
__device__ float g_vf[NQ];
__device__ float g_if[NQ];

typedef unsigned long long ull;

__device__ __forceinline__ float warp_sum(float v) {
    #pragma unroll
    for (int o = 16; o; o >>= 1) v += __shfl_xor_sync(FULLM, v, o);
    return v;
}
__device__ __forceinline__ float warp_max(float v) {
    #pragma unroll
    for (int o = 16; o; o >>= 1) v = fmaxf(v, __shfl_xor_sync(FULLM, v, o));
    return v;
}
// paired reduce: after pair_seed + 4-level butterfly, EVEN lanes hold sum(a),
// ODD lanes hold sum(b)
__device__ __forceinline__ float pair_seed(float a, float b, int lane) {
    float x = (lane & 1) ? a : b;
    x = __shfl_xor_sync(FULLM, x, 1);
    return ((lane & 1) ? b : a) + x;
}
__device__ __forceinline__ float pair_reduce(float a, float b, int lane) {
    float cr = pair_seed(a, b, lane);
    #pragma unroll
    for (int o = 2; o < 32; o <<= 1) cr += __shfl_xor_sync(FULLM, cr, o);
    return cr;
}
// ---- packed f32x2 helpers (sm_100+) --------------------------------------------
__device__ __forceinline__ ull pack2(float x) {
    ull r; asm("mov.b64 %0, {%1,%1};" : "=l"(r) : "f"(x)); return r;
}
__device__ __forceinline__ ull fma2(ull a, ull b, ull c) {
    ull d; asm("fma.rn.f32x2 %0, %1, %2, %3;" : "=l"(d) : "l"(a), "l"(b), "l"(c));
    return d;
}
__device__ __forceinline__ void unpack2(ull p, float& lo, float& hi) {
    asm("mov.b64 {%0,%1}, %2;" : "=f"(lo), "=f"(hi) : "l"(p));
}
__device__ __forceinline__ float hadd2(ull p) {
    float lo, hi; unpack2(p, lo, hi); return lo + hi;
}
__device__ __forceinline__ ull dotu2(ulonglong2 a, ulonglong2 b, ull acc) {
    acc = fma2(a.x, b.x, acc);
    return fma2(a.y, b.y, acc);
}

// ---------------- per-class body (one 512-thread half) --------------------------
template<bool SM>
__device__ __forceinline__ void class_body(
    int c, int n_c, int half, int ltid,
    const float* __restrict__ tokens,
    float* __restrict__ out,
    const float* sp, const int* IDX,
    float* S, float* V, float* IV,
    float* su, float* red, float* sinv)
{
    int wid = ltid >> 5, lane = ltid & 31;

    // --- phase A: TWO rows per warp iteration; f32x2 dots; paired reduce ---------
    for (int i0 = 2 * wid; i0 < n_c; i0 += 32) {
        int i1 = i0 + 1;
        bool has2 = (i1 < n_c);                    // warp-uniform
        int n0 = IDX[i0];
        int n1 = IDX[has2 ? i1 : i0];
        const ulonglong2* ta = (const ulonglong2*)(tokens + (size_t)n0 * EMBED_D);
        const ulonglong2* tb = (const ulonglong2*)(tokens + (size_t)n1 * EMBED_D);
        ulonglong2 t0 = ta[lane], t1 = ta[lane + 32], t2 = ta[lane + 64], t3 = ta[lane + 96];
        ulonglong2 u0 = tb[lane], u1 = tb[lane + 32], u2 = tb[lane + 64], u3 = tb[lane + 96];
        ull sa = dotu2(t0, t0, 0ULL); sa = dotu2(t1, t1, sa);
        sa = dotu2(t2, t2, sa);       sa = dotu2(t3, t3, sa);
        ull sb = dotu2(u0, u0, 0ULL); sb = dotu2(u1, u1, sb);
        sb = dotu2(u2, u2, sb);       sb = dotu2(u3, u3, sb);
        float ssp = pair_reduce(hadd2(sa), hadd2(sb), lane);   // even: r0, odd: r1
        float inv = rsqrtf(ssp);
        if (lane == 0) IV[i0] = inv;
        else if (lane == 1 && has2) IV[i1] = inv;
        #pragma unroll
        for (int j = 0; j < NUM_PROTO; j++) {
            const ulonglong2* pp = (const ulonglong2*)(sp + j * EMBED_D);
            ulonglong2 p0 = pp[lane], p1 = pp[lane + 32], p2 = pp[lane + 64], p3 = pp[lane + 96];
            ull da = dotu2(t0, p0, 0ULL); da = dotu2(t1, p1, da);
            da = dotu2(t2, p2, da);       da = dotu2(t3, p3, da);
            ull db = dotu2(u0, p0, 0ULL); db = dotu2(u1, p1, db);
            db = dotu2(u2, p2, db);       db = dotu2(u3, p3, db);
            float dp = pair_reduce(hadd2(da), hadd2(db), lane);  // even: r0, odd: r1
            if (lane == 0) S[i0 * SROW + j] = dp * inv;
            else if (lane == 1 && has2) S[i1 * SROW + j] = dp * inv;
        }
    }
    HBAR(half);

    // --- phase B: 5 Sinkhorn iterations; final v-update emits weights directly ---
    // (w_j / sum_j w_j == e_j / ss with e_j = exp((S+su-mm)/eps): the V/mm factor
    //  cancels, so phase C is folded in here for free.)
    if (wid < NUM_PROTO) {
        const float log_a = __logf(1.0f / (float)NUM_PROTO + EPS_LOG);
        const float log_b = __logf(1.0f / (float)n_c + EPS_LOG);
        for (int it = 0; it < ITERS; it++) {
            int j = wid;                       // u: warp j, two-pass max -> sum LSE
            float m = -FLT_MAX;
            if (it == 0) {                     // V == 0 on first iteration
                for (int i = lane; i < n_c; i += 32)
                    m = fmaxf(m, S[i * SROW + j]);
            } else {
                for (int i = lane; i < n_c; i += 32)
                    m = fmaxf(m, S[i * SROW + j] + V[i]);
            }
            m = warp_max(m);
            float s = 0.0f;
            if (it == 0) {
                for (int i = lane; i < n_c; i += 32)
                    s += __expf((S[i * SROW + j] - m) * INV_EPS);
            } else {
                for (int i = lane; i < n_c; i += 32)
                    s += __expf((S[i * SROW + j] + V[i] - m) * INV_EPS);
            }
            s = warp_sum(s);
            if (lane == 0) su[j] = EPSF * log_a - m - EPSF * __logf(s);
            B320(half);
            if (it < ITERS - 1) {
                for (int i = ltid; i < n_c; i += 320) {   // v: thread per row
                    const float4 s0 = *(const float4*)(S + i * SROW);
                    const float4 s1 = *(const float4*)(S + i * SROW + 4);
                    const float2 s2 = *(const float2*)(S + i * SROW + 8);
                    float b[NUM_PROTO] = {
                        s0.x + su[0], s0.y + su[1], s0.z + su[2], s0.w + su[3],
                        s1.x + su[4], s1.y + su[5], s1.z + su[6], s1.w + su[7],
                        s2.x + su[8], s2.y + su[9] };
                    float mm = b[0];
                    #pragma unroll
                    for (int j2 = 1; j2 < NUM_PROTO; j2++) mm = fmaxf(mm, b[j2]);
                    float ss = 0.0f;
                    #pragma unroll
                    for (int j2 = 0; j2 < NUM_PROTO; j2++) ss += __expf((b[j2] - mm) * INV_EPS);
                    V[i] = EPSF * log_b - mm - EPSF * __logf(ss);
                }
                B320(half);
            } else {
                // final v-update fused with phase C: store normalized weights * IV
                for (int i = ltid; i < n_c; i += 320) {
                    const float4 s0 = *(const float4*)(S + i * SROW);
                    const float4 s1 = *(const float4*)(S + i * SROW + 4);
                    const float2 s2 = *(const float2*)(S + i * SROW + 8);
                    float b[NUM_PROTO] = {
                        s0.x + su[0], s0.y + su[1], s0.z + su[2], s0.w + su[3],
                        s1.x + su[4], s1.y + su[5], s1.z + su[6], s1.w + su[7],
                        s2.x + su[8], s2.y + su[9] };
                    float mm = b[0];
                    #pragma unroll
                    for (int j2 = 1; j2 < NUM_PROTO; j2++) mm = fmaxf(mm, b[j2]);
                    float e[NUM_PROTO];
                    float ss = 0.0f;
                    #pragma unroll
                    for (int j2 = 0; j2 < NUM_PROTO; j2++) {
                        e[j2] = __expf((b[j2] - mm) * INV_EPS);
                        ss += e[j2];
                    }
                    float sc = IV[i] / ss;     // fold 1/||tok|| for raw-token phase D
                    *(float4*)(S + i * SROW)     = make_float4(e[0]*sc, e[1]*sc, e[2]*sc, e[3]*sc);
                    *(float4*)(S + i * SROW + 4) = make_float4(e[4]*sc, e[5]*sc, e[6]*sc, e[7]*sc);
                    *(float2*)(S + i * SROW + 8) = make_float2(e[8]*sc, e[9]*sc);
                }
            }
        }
    }
    HBAR(half);   // warps 10-15 rejoin; weights visible

    // --- phase D: packed f32x2 accumulation (thread owns dim d) ---
    int d = ltid;
    ull acc2[5];
    #pragma unroll
    for (int h = 0; h < 5; h++) acc2[h] = 0ULL;

    #define DROW(ii, tv) {                                          \
        const ulonglong2 A = *(const ulonglong2*)(S + (ii) * SROW); \
        const ulonglong2 B = *(const ulonglong2*)(S + (ii) * SROW + 4); \
        const ull C = *(const ull*)(S + (ii) * SROW + 8);           \
        ull tt = pack2(tv);                                         \
        acc2[0] = fma2(A.x, tt, acc2[0]);                           \
        acc2[1] = fma2(A.y, tt, acc2[1]);                           \
        acc2[2] = fma2(B.x, tt, acc2[2]);                           \
        acc2[3] = fma2(B.y, tt, acc2[3]);                           \
        acc2[4] = fma2(C,   tt, acc2[4]); }

    int i = 0;
    for (; i + 4 <= n_c; i += 4) {               // 4 L1-warm loads in flight
        float t0 = __ldg(tokens + (size_t)IDX[i]     * EMBED_D + d);
        float t1 = __ldg(tokens + (size_t)IDX[i + 1] * EMBED_D + d);
        float t2 = __ldg(tokens + (size_t)IDX[i + 2] * EMBED_D + d);
        float t3 = __ldg(tokens + (size_t)IDX[i + 3] * EMBED_D + d);
        DROW(i,     t0); DROW(i + 1, t1);
        DROW(i + 2, t2); DROW(i + 3, t3);
    }
    for (; i < n_c; i++) {
        float t0 = __ldg(tokens + (size_t)IDX[i] * EMBED_D + d);
        DROW(i, t0);
    }
    #undef DROW
    float acc[NUM_PROTO];
    #pragma unroll
    for (int h = 0; h < 5; h++) unpack2(acc2[h], acc[2*h], acc[2*h+1]);

    // --- phase E: momentum blend + PAIRED l2-norm reductions + writeout ---
    float r[NUM_PROTO];
    #pragma unroll
    for (int j = 0; j < NUM_PROTO; j++)
        r[j] = 0.98f * sp[j * EMBED_D + d] + 0.02f * acc[j];
    {
        float cr[5];
        #pragma unroll
        for (int p = 0; p < 5; p++)
            cr[p] = pair_seed(r[2*p] * r[2*p], r[2*p+1] * r[2*p+1], lane);
        #pragma unroll
        for (int o = 2; o < 32; o <<= 1) {
            #pragma unroll
            for (int p = 0; p < 5; p++) cr[p] += __shfl_xor_sync(FULLM, cr[p], o);
        }
        if (lane < 2) {
            #pragma unroll
            for (int p = 0; p < 5; p++) red[wid * NUM_PROTO + 2*p + lane] = cr[p];
        }
    }
    HBAR(half);
    if (wid < NUM_PROTO) {
        int j = wid;
        float y = (lane < 16) ? red[lane * NUM_PROTO + j] : 0.0f;
        y = warp_sum(y);
        if (lane == 0) sinv[j] = rsqrtf(y);
    }
    HBAR(half);
    #pragma unroll
    for (int j = 0; j < NUM_PROTO; j++)
        out[(size_t)(c * NUM_PROTO + j) * EMBED_D + d] = r[j] * sinv[j];
}

// ---------------- fused kernel: 2 classes per block, shared label scan ----------
__global__ void __launch_bounds__(1024, 1)
k_main(const float* __restrict__ tokens,
       const void*  __restrict__ labels_raw,
       const float* __restrict__ protos,
       float* __restrict__ out) {
    extern __shared__ __align__(16) char dyn[];

    int tid  = threadIdx.x;
    int half = tid >> 9;
    int ltid = tid & 511;
    int wid  = ltid >> 5, lane = ltid & 31;
    int fw   = tid >> 5;                       // full-block warp id 0..31
    int c0   = blockIdx.x * 2, c1 = c0 + 1;
    int c    = c0 + half;

    char* hb  = dyn + half * HALF_BYTES;
    float*    sp    = (float*)(hb + OFF_SP);
    float*    ssS   = (float*)(hb + OFF_SSS);
    float*    ssV   = (float*)(hb + OFF_SSV);
    float*    ssI   = (float*)(hb + OFF_SSI);
    int*      sidx  = (int*)  (hb + OFF_SIDX);
    unsigned* cmask = (unsigned*)(hb + OFF_CMASK);
    int*      cpre  = (int*)  (hb + OFF_CPRE);
    int*      wsum  = (int*)  (hb + OFF_WSUM);
    float*    su    = (float*)(hb + OFF_SU);
    float*    red   = (float*)(hb + OFF_RED);
    float*    sinv  = (float*)(hb + OFF_SINV);
    int*      s_n   = (int*)  (hb + OFF_SN);
    int*      s_lt  = s_n + 1;
    unsigned* cm0   = (unsigned*)(dyn + OFF_CMASK);
    unsigned* cm1   = (unsigned*)(dyn + HALF_BYTES + OFF_CMASK);
    int*      lt0   = (int*)(dyn + OFF_SN) + 1;
    int*      lt1   = (int*)(dyn + HALF_BYTES + OFF_SN) + 1;

    // stage this half's prototypes (DRAM loads in flight during label scan)
    {
        const float4* pg = (const float4*)(protos + (size_t)c * NUM_PROTO * EMBED_D);
        float4* ps = (float4*)sp;
        for (int i = ltid; i < NUM_PROTO * EMBED_D / 4; i += 512) ps[i] = pg[i];
    }
    if (ltid == 0) *s_lt = 0;

    // per-warp label dtype detection (uniform branch, hoisted out of load loops)
    const long long* l64 = (const long long*)labels_raw;
    bool is64;
    {
        long long v = l64[lane];
        unsigned bal = __ballot_sync(FULLM, v >= 0 && v < NUM_CLASSES);
        is64 = (__popc(bal) >= 16);
    }
    __syncthreads();   // s_lt init visible block-wide before shared scan

    // --- shared pass 1: all 32 warps scan labels ONCE, masks for both classes ---
    const int4* l4 = (const int4*)labels_raw;
    int ltl0 = 0, ltl1 = 0;
    if (!is64) {
        #pragma unroll
        for (int k = 0; k < 2; k++) {            // 2 int4 per thread = 8192 labels
            int4 v = l4[tid + 1024 * k];
            unsigned a0 = __ballot_sync(FULLM, v.x == c0);
            unsigned a1 = __ballot_sync(FULLM, v.y == c0);
            unsigned a2 = __ballot_sync(FULLM, v.z == c0);
            unsigned a3 = __ballot_sync(FULLM, v.w == c0);
            unsigned b0 = __ballot_sync(FULLM, v.x == c1);
            unsigned b1 = __ballot_sync(FULLM, v.y == c1);
            unsigned b2 = __ballot_sync(FULLM, v.z == c1);
            unsigned b3 = __ballot_sync(FULLM, v.w == c1);
            unsigned p0 = __ballot_sync(FULLM, v.x < c0);
            unsigned p1 = __ballot_sync(FULLM, v.y < c0);
            unsigned p2 = __ballot_sync(FULLM, v.z < c0);
            unsigned p3 = __ballot_sync(FULLM, v.w < c0);
            unsigned q0 = __ballot_sync(FULLM, v.x < c1);
            unsigned q1 = __ballot_sync(FULLM, v.y < c1);
            unsigned q2 = __ballot_sync(FULLM, v.z < c1);
            unsigned q3 = __ballot_sync(FULLM, v.w < c1);
            if ((tid & 31) == 0) {
                int mb = (k * 32 + fw) * 4;
                cm0[mb] = a0; cm0[mb+1] = a1; cm0[mb+2] = a2; cm0[mb+3] = a3;
                cm1[mb] = b0; cm1[mb+1] = b1; cm1[mb+2] = b2; cm1[mb+3] = b3;
                ltl0 += __popc(p0) + __popc(p1) + __popc(p2) + __popc(p3);
                ltl1 += __popc(q0) + __popc(q1) + __popc(q2) + __popc(q3);
            }
        }
    } else {
        #pragma unroll
        for (int k = 0; k < 4; k++) {            // int4 = 2 int64 labels (.x, .z)
            int4 v = l4[tid + 1024 * k];
            unsigned a0 = __ballot_sync(FULLM, v.x == c0);
            unsigned a1 = __ballot_sync(FULLM, v.z == c0);
            unsigned b0 = __ballot_sync(FULLM, v.x == c1);
            unsigned b1 = __ballot_sync(FULLM, v.z == c1);
            unsigned p0 = __ballot_sync(FULLM, v.x < c0);
            unsigned p1 = __ballot_sync(FULLM, v.z < c0);
            unsigned q0 = __ballot_sync(FULLM, v.x < c1);
            unsigned q1 = __ballot_sync(FULLM, v.z < c1);
            if ((tid & 31) == 0) {
                int mb = (k * 32 + fw) * 2;
                cm0[mb] = a0; cm0[mb+1] = a1;
                cm1[mb] = b0; cm1[mb+1] = b1;
                ltl0 += __popc(p0) + __popc(p1);
                ltl1 += __popc(q0) + __popc(q1);
            }
        }
    }
    if ((tid & 31) == 0) {
        if (ltl0) atomicAdd(lt0, ltl0);          // int: deterministic
        if (ltl1) atomicAdd(lt1, ltl1);
    }
    __syncthreads();   // masks + lt visible; halves independent from here on

    // --- two-level exclusive prefix over 256 mask popcounts (per half) ---
    if (wid < 8) {
        int v = __popc(cmask[wid * 32 + lane]);
        int inc = v;
        #pragma unroll
        for (int o = 1; o < 32; o <<= 1) {
            int t = __shfl_up_sync(FULLM, inc, o);
            if (lane >= o) inc += t;
        }
        cpre[wid * 32 + lane] = inc - v;
        if (lane == 31) wsum[wid] = inc;
    }
    HBAR(half);
    if (wid == 0 && lane < 8) {
        int v = wsum[lane];
        int inc = v;
        #pragma unroll
        for (int o = 1; o < 8; o <<= 1) {
            int t = __shfl_up_sync(0xffu, inc, o);
            if (lane >= o) inc += t;
        }
        wsum[lane] = inc - v;
        if (lane == 7) *s_n = inc;
    }
    HBAR(half);

    int n_c = *s_n;
    if (n_c == 0) {   // out = l2norm(0.98*proto) = proto (unit-norm input)
        #pragma unroll
        for (int j = 0; j < NUM_PROTO; j++)
            out[(size_t)(c * NUM_PROTO + j) * EMBED_D + ltid] = sp[j * EMBED_D + ltid];
        return;
    }
    bool sm  = (n_c <= NCAP);
    int  off = *s_lt;
    int* dst = sm ? sidx : (g_fidx + off);

    // --- pass 2: replay cached masks; thread per sub-chunk, no label reloads ---
    if (ltid < 256) {
        unsigned m = cmask[ltid];
        if (m) {
            int pos = wsum[ltid >> 5] + cpre[ltid];
            int base;
            int mult = is64 ? 2 : 4;
            if (!is64) {
                int k = ltid >> 7, w = (ltid >> 2) & 31, cc = ltid & 3;
                base = 4 * (32 * w + 1024 * k) + cc;
            } else {
                int k = ltid >> 6, w = (ltid >> 1) & 31, cc = ltid & 1;
                base = 2 * (32 * w + 1024 * k) + cc;
            }
            while (m) {
                int l = __ffs(m) - 1; m &= m - 1;
                dst[pos++] = base + mult * l;
            }
        }
    }
    HBAR(half);

    if (sm) {
        class_body<true >(c, n_c, half, ltid, tokens, out, sp, sidx,
                          ssS, ssV, ssI, su, red, sinv);
    } else {  // statistically unreachable; correct fallback via global scratch
        class_body<false>(c, n_c, half, ltid, tokens, out, sp, g_fidx + off,
                          g_Sf + (size_t)off * SROW, g_vf + off, g_if + off,
                          su, red, sinv);
    }
}

// -------------------------------- launch ---------------------------------------
extern "C" void kernel_launch(void* const* d_in, const int* in_sizes, int n_in,
                              void* d_out, int out_size) {
    const float* tokens = (const float*)d_in[0];
    const void*  labels = d_in[1];
    const float* protos = (const float*)d_in[2];
    float* out = (float*)d_out;

    cudaFuncSetAttribute(k_main, cudaFuncAttributeMaxDynamicSharedMemorySize,
                         SMEM_TOTAL);
    k_main<<<NUM_CLASSES / 2, 1024, SMEM_TOTAL>>>(tokens, labels, protos, out);
}

// round 17
// speedup vs baseline: 1.0666x; 1.0042x over previous
#include <cuda_runtime.h>
#include <math.h>
#include <float.h>

#define NUM_CLASSES 200
#define NUM_PROTO   10
#define EMBED_D     512
#define NQ          8192
#define ITERS       5
#define EPSF        0.01f
#define INV_EPS     100.0f
#define EPS_LOG     1e-8f
#define NCAP        192           // per-class row capacity (mean n_c ~41, sd 6.4)
#define SROW        12            // padded S row stride (16B-aligned)
#define FULLM       0xffffffffu

// per-half barriers: ids 1,2 = 512-thread half-sync; ids 3,4 = 320-thread Sinkhorn
#define HBAR(h) asm volatile("bar.sync %0, 512;" :: "r"(1 + (h)) : "memory")
#define B320(h) asm volatile("bar.sync %0, 320;" :: "r"(3 + (h)) : "memory")

// ---- dynamic smem layout (per half; byte offsets, 16B-aligned) -----------------
#define OFF_SP     0                                  // float [10*512]  20480 B
#define OFF_SSS    (OFF_SP   + NUM_PROTO*EMBED_D*4)   // float [192*12]   9216 B
#define OFF_SSV    (OFF_SSS  + NCAP*SROW*4)
#define OFF_SSI    (OFF_SSV  + NCAP*4)
#define OFF_SIDX   (OFF_SSI  + NCAP*4)
#define OFF_CMASK  (OFF_SIDX + NCAP*4)                // uint [256]
#define OFF_CPRE   (OFF_CMASK+ 256*4)                 // int  [256]
#define OFF_WSUM   (OFF_CPRE + 256*4)                 // int  [8]
#define OFF_SU     (OFF_WSUM + 8*4)                   // float[10]+pad
#define OFF_RED    (OFF_SU   + 48)                    // float[160]
#define OFF_SINV   (OFF_RED  + 160*4)                 // float[10]+pad
#define OFF_SN     (OFF_SINV + 48)                    // int s_n, s_lt
#define HALF_BYTES (OFF_SN + 16)                      // = 34832
#define SMEM_TOTAL (2 * HALF_BYTES)                   // = 69664 (< 228 KB)

// ---- fallback scratch (only if a class exceeds NCAP rows; statistically unreachable)
__device__ int   g_fidx[NQ];
__device__ float g_Sf[NQ * SROW];
__device__ float g_vf[NQ];
__device__ float g_if[NQ];

typedef unsigned long long ull;

__device__ __forceinline__ float warp_sum(float v) {
    #pragma unroll
    for (int o = 16; o; o >>= 1) v += __shfl_xor_sync(FULLM, v, o);
    return v;
}
__device__ __forceinline__ float warp_max(float v) {
    #pragma unroll
    for (int o = 16; o; o >>= 1) v = fmaxf(v, __shfl_xor_sync(FULLM, v, o));
    return v;
}
// paired reduce: EVEN lanes end with sum(a), ODD lanes sum(b)
__device__ __forceinline__ float pair_seed(float a, float b, int lane) {
    float x = (lane & 1) ? a : b;
    x = __shfl_xor_sync(FULLM, x, 1);
    return ((lane & 1) ? b : a) + x;
}
__device__ __forceinline__ float pair_reduce(float a, float b, int lane) {
    float cr = pair_seed(a, b, lane);
    #pragma unroll
    for (int o = 2; o < 32; o <<= 1) cr += __shfl_xor_sync(FULLM, cr, o);
    return cr;
}
// quad reduce: lane%4==0 -> sum(a), 1 -> sum(b), 2 -> sum(c), 3 -> sum(d)
__device__ __forceinline__ float quad_reduce(float a, float b, float c, float d, int lane) {
    float x = (lane & 1) ? a : b;  x = __shfl_xor_sync(FULLM, x, 1);
    float ab = ((lane & 1) ? b : a) + x;
    float y = (lane & 1) ? c : d;  y = __shfl_xor_sync(FULLM, y, 1);
    float cd = ((lane & 1) ? d : c) + y;
    float z = (lane & 2) ? ab : cd; z = __shfl_xor_sync(FULLM, z, 2);
    float q = ((lane & 2) ? cd : ab) + z;
    #pragma unroll
    for (int o = 4; o < 32; o <<= 1) q += __shfl_xor_sync(FULLM, q, o);
    return q;
}
// ---- packed f32x2 helpers (sm_100+) --------------------------------------------
__device__ __forceinline__ ull pack2(float x) {
    ull r; asm("mov.b64 %0, {%1,%1};" : "=l"(r) : "f"(x)); return r;
}
__device__ __forceinline__ ull fma2(ull a, ull b, ull c) {
    ull d; asm("fma.rn.f32x2 %0, %1, %2, %3;" : "=l"(d) : "l"(a), "l"(b), "l"(c));
    return d;
}
__device__ __forceinline__ void unpack2(ull p, float& lo, float& hi) {
    asm("mov.b64 {%0,%1}, %2;" : "=f"(lo), "=f"(hi) : "l"(p));
}
__device__ __forceinline__ float hadd2(ull p) {
    float lo, hi; unpack2(p, lo, hi); return lo + hi;
}
__device__ __forceinline__ ull dotu2(ulonglong2 a, ulonglong2 b, ull acc) {
    acc = fma2(a.x, b.x, acc);
    return fma2(a.y, b.y, acc);
}

// ---------------- per-class body (one 512-thread half) --------------------------
template<bool SM>
__device__ __forceinline__ void class_body(
    int c, int n_c, int half, int ltid,
    const float* __restrict__ tokens,
    float* __restrict__ out,
    const float* sp, const int* IDX,
    float* S, float* V, float* IV,
    float* su, float* red, float* sinv)
{
    int wid = ltid >> 5, lane = ltid & 31;

    // --- phase A: TWO rows/warp-iter; f32x2 dots; quad reductions ----------------
    for (int i0 = 2 * wid; i0 < n_c; i0 += 32) {
        int i1 = i0 + 1;
        bool has2 = (i1 < n_c);                    // warp-uniform
        int n0 = IDX[i0];
        int n1 = IDX[has2 ? i1 : i0];
        const ulonglong2* ta = (const ulonglong2*)(tokens + (size_t)n0 * EMBED_D);
        const ulonglong2* tb = (const ulonglong2*)(tokens + (size_t)n1 * EMBED_D);
        ulonglong2 t0 = ta[lane], t1 = ta[lane + 32], t2 = ta[lane + 64], t3 = ta[lane + 96];
        ulonglong2 u0 = tb[lane], u1 = tb[lane + 32], u2 = tb[lane + 64], u3 = tb[lane + 96];
        // quad 0: (ss0, ss1, d0_r0, d0_r1)
        float inv0, inv1;
        {
            ull sa = dotu2(t0, t0, 0ULL); sa = dotu2(t1, t1, sa);
            sa = dotu2(t2, t2, sa);       sa = dotu2(t3, t3, sa);
            ull sb = dotu2(u0, u0, 0ULL); sb = dotu2(u1, u1, sb);
            sb = dotu2(u2, u2, sb);       sb = dotu2(u3, u3, sb);
            const ulonglong2* pp = (const ulonglong2*)sp;
            ulonglong2 p0 = pp[lane], p1 = pp[lane + 32], p2 = pp[lane + 64], p3 = pp[lane + 96];
            ull da = dotu2(t0, p0, 0ULL); da = dotu2(t1, p1, da);
            da = dotu2(t2, p2, da);       da = dotu2(t3, p3, da);
            ull db = dotu2(u0, p0, 0ULL); db = dotu2(u1, p1, db);
            db = dotu2(u2, p2, db);       db = dotu2(u3, p3, db);
            float q0 = quad_reduce(hadd2(sa), hadd2(sb), hadd2(da), hadd2(db), lane);
            inv0 = rsqrtf(__shfl_sync(FULLM, q0, 0));
            inv1 = rsqrtf(__shfl_sync(FULLM, q0, 1));
            if (lane == 0) IV[i0] = inv0;
            else if (lane == 1 && has2) IV[i1] = inv1;
            else if (lane == 2) S[i0 * SROW + 0] = q0 * inv0;
            else if (lane == 3 && has2) S[i1 * SROW + 0] = q0 * inv1;
        }
        // quads 1..4: j pairs (1,2) (3,4) (5,6) (7,8)
        #pragma unroll
        for (int jp = 0; jp < 4; jp++) {
            int j0 = 1 + 2 * jp, j1 = j0 + 1;
            ull da, db;
            {
                const ulonglong2* pp = (const ulonglong2*)(sp + j0 * EMBED_D);
                ulonglong2 p0 = pp[lane], p1 = pp[lane + 32], p2 = pp[lane + 64], p3 = pp[lane + 96];
                da = dotu2(t0, p0, 0ULL); da = dotu2(t1, p1, da);
                da = dotu2(t2, p2, da);   da = dotu2(t3, p3, da);
                db = dotu2(u0, p0, 0ULL); db = dotu2(u1, p1, db);
                db = dotu2(u2, p2, db);   db = dotu2(u3, p3, db);
            }
            ull dc, dd;
            {
                const ulonglong2* pp = (const ulonglong2*)(sp + j1 * EMBED_D);
                ulonglong2 p0 = pp[lane], p1 = pp[lane + 32], p2 = pp[lane + 64], p3 = pp[lane + 96];
                dc = dotu2(t0, p0, 0ULL); dc = dotu2(t1, p1, dc);
                dc = dotu2(t2, p2, dc);   dc = dotu2(t3, p3, dc);
                dd = dotu2(u0, p0, 0ULL); dd = dotu2(u1, p1, dd);
                dd = dotu2(u2, p2, dd);   dd = dotu2(u3, p3, dd);
            }
            float q = quad_reduce(hadd2(da), hadd2(db), hadd2(dc), hadd2(dd), lane);
            if (lane == 0) S[i0 * SROW + j0] = q * inv0;
            else if (lane == 1 && has2) S[i1 * SROW + j0] = q * inv1;
            else if (lane == 2) S[i0 * SROW + j1] = q * inv0;
            else if (lane == 3 && has2) S[i1 * SROW + j1] = q * inv1;
        }
        // j = 9: plain pair
        {
            const ulonglong2* pp = (const ulonglong2*)(sp + 9 * EMBED_D);
            ulonglong2 p0 = pp[lane], p1 = pp[lane + 32], p2 = pp[lane + 64], p3 = pp[lane + 96];
            ull da = dotu2(t0, p0, 0ULL); da = dotu2(t1, p1, da);
            da = dotu2(t2, p2, da);       da = dotu2(t3, p3, da);
            ull db = dotu2(u0, p0, 0ULL); db = dotu2(u1, p1, db);
            db = dotu2(u2, p2, db);       db = dotu2(u3, p3, db);
            float p = pair_reduce(hadd2(da), hadd2(db), lane);
            if (lane == 0) S[i0 * SROW + 9] = p * inv0;
            else if (lane == 1 && has2) S[i1 * SROW + 9] = p * inv1;
        }
    }
    HBAR(half);

    // --- phase B: 5 Sinkhorn iterations; final v-update emits weights directly ---
    if (wid < NUM_PROTO) {
        const float log_a = __logf(1.0f / (float)NUM_PROTO + EPS_LOG);
        const float log_b = __logf(1.0f / (float)n_c + EPS_LOG);
        for (int it = 0; it < ITERS; it++) {
            int j = wid;                       // u: warp j, two-pass max -> sum LSE
            float m = -FLT_MAX;
            if (it == 0) {                     // V == 0 on first iteration
                for (int i = lane; i < n_c; i += 32)
                    m = fmaxf(m, S[i * SROW + j]);
            } else {
                for (int i = lane; i < n_c; i += 32)
                    m = fmaxf(m, S[i * SROW + j] + V[i]);
            }
            m = warp_max(m);
            float s = 0.0f;
            if (it == 0) {
                for (int i = lane; i < n_c; i += 32)
                    s += __expf((S[i * SROW + j] - m) * INV_EPS);
            } else {
                for (int i = lane; i < n_c; i += 32)
                    s += __expf((S[i * SROW + j] + V[i] - m) * INV_EPS);
            }
            s = warp_sum(s);
            if (lane == 0) su[j] = EPSF * log_a - m - EPSF * __logf(s);
            B320(half);
            if (it < ITERS - 1) {
                for (int i = ltid; i < n_c; i += 320) {   // v: thread per row
                    const float4 s0 = *(const float4*)(S + i * SROW);
                    const float4 s1 = *(const float4*)(S + i * SROW + 4);
                    const float2 s2 = *(const float2*)(S + i * SROW + 8);
                    float b[NUM_PROTO] = {
                        s0.x + su[0], s0.y + su[1], s0.z + su[2], s0.w + su[3],
                        s1.x + su[4], s1.y + su[5], s1.z + su[6], s1.w + su[7],
                        s2.x + su[8], s2.y + su[9] };
                    float mm = b[0];
                    #pragma unroll
                    for (int j2 = 1; j2 < NUM_PROTO; j2++) mm = fmaxf(mm, b[j2]);
                    float ss = 0.0f;
                    #pragma unroll
                    for (int j2 = 0; j2 < NUM_PROTO; j2++) ss += __expf((b[j2] - mm) * INV_EPS);
                    V[i] = EPSF * log_b - mm - EPSF * __logf(ss);
                }
                B320(half);
            } else {
                // final v fused with normalization: store weights * IV (phase C free)
                for (int i = ltid; i < n_c; i += 320) {
                    const float4 s0 = *(const float4*)(S + i * SROW);
                    const float4 s1 = *(const float4*)(S + i * SROW + 4);
                    const float2 s2 = *(const float2*)(S + i * SROW + 8);
                    float b[NUM_PROTO] = {
                        s0.x + su[0], s0.y + su[1], s0.z + su[2], s0.w + su[3],
                        s1.x + su[4], s1.y + su[5], s1.z + su[6], s1.w + su[7],
                        s2.x + su[8], s2.y + su[9] };
                    float mm = b[0];
                    #pragma unroll
                    for (int j2 = 1; j2 < NUM_PROTO; j2++) mm = fmaxf(mm, b[j2]);
                    float e[NUM_PROTO];
                    float ss = 0.0f;
                    #pragma unroll
                    for (int j2 = 0; j2 < NUM_PROTO; j2++) {
                        e[j2] = __expf((b[j2] - mm) * INV_EPS);
                        ss += e[j2];
                    }
                    float sc = IV[i] / ss;     // fold 1/||tok|| for raw-token phase D
                    *(float4*)(S + i * SROW)     = make_float4(e[0]*sc, e[1]*sc, e[2]*sc, e[3]*sc);
                    *(float4*)(S + i * SROW + 4) = make_float4(e[4]*sc, e[5]*sc, e[6]*sc, e[7]*sc);
                    *(float2*)(S + i * SROW + 8) = make_float2(e[8]*sc, e[9]*sc);
                }
            }
        }
    }
    HBAR(half);   // warps 10-15 rejoin; weights visible

    // --- phase D: packed f32x2 accumulation (thread owns dim d) ---
    int d = ltid;
    ull acc2[5];
    #pragma unroll
    for (int h = 0; h < 5; h++) acc2[h] = 0ULL;

    #define DROW(ii, tv) {                                          \
        const ulonglong2 A = *(const ulonglong2*)(S + (ii) * SROW); \
        const ulonglong2 B = *(const ulonglong2*)(S + (ii) * SROW + 4); \
        const ull C = *(const ull*)(S + (ii) * SROW + 8);           \
        ull tt = pack2(tv);                                         \
        acc2[0] = fma2(A.x, tt, acc2[0]);                           \
        acc2[1] = fma2(A.y, tt, acc2[1]);                           \
        acc2[2] = fma2(B.x, tt, acc2[2]);                           \
        acc2[3] = fma2(B.y, tt, acc2[3]);                           \
        acc2[4] = fma2(C,   tt, acc2[4]); }

    int i = 0;
    for (; i + 4 <= n_c; i += 4) {               // 4 L1-warm loads in flight
        float t0 = __ldg(tokens + (size_t)IDX[i]     * EMBED_D + d);
        float t1 = __ldg(tokens + (size_t)IDX[i + 1] * EMBED_D + d);
        float t2 = __ldg(tokens + (size_t)IDX[i + 2] * EMBED_D + d);
        float t3 = __ldg(tokens + (size_t)IDX[i + 3] * EMBED_D + d);
        DROW(i,     t0); DROW(i + 1, t1);
        DROW(i + 2, t2); DROW(i + 3, t3);
    }
    for (; i < n_c; i++) {
        float t0 = __ldg(tokens + (size_t)IDX[i] * EMBED_D + d);
        DROW(i, t0);
    }
    #undef DROW
    float acc[NUM_PROTO];
    #pragma unroll
    for (int h = 0; h < 5; h++) unpack2(acc2[h], acc[2*h], acc[2*h+1]);

    // --- phase E: momentum blend + QUAD l2-norm reductions + writeout ---
    float r[NUM_PROTO];
    #pragma unroll
    for (int j = 0; j < NUM_PROTO; j++)
        r[j] = 0.98f * sp[j * EMBED_D + d] + 0.02f * acc[j];
    {
        float q0 = quad_reduce(r[0]*r[0], r[1]*r[1], r[2]*r[2], r[3]*r[3], lane);
        float q1 = quad_reduce(r[4]*r[4], r[5]*r[5], r[6]*r[6], r[7]*r[7], lane);
        float q2 = pair_reduce(r[8]*r[8], r[9]*r[9], lane);
        if (lane < 4)                 red[wid * NUM_PROTO + lane] = q0;       // r0..r3
        else if (lane < 8)            red[wid * NUM_PROTO + lane] = q1;       // r4..r7
        else if (lane == 8 || lane == 9) red[wid * NUM_PROTO + lane] = q2;    // r8, r9
    }
    HBAR(half);
    if (wid < NUM_PROTO) {
        int j = wid;
        float y = (lane < 16) ? red[lane * NUM_PROTO + j] : 0.0f;
        y = warp_sum(y);
        if (lane == 0) sinv[j] = rsqrtf(y);
    }
    HBAR(half);
    #pragma unroll
    for (int j = 0; j < NUM_PROTO; j++)
        out[(size_t)(c * NUM_PROTO + j) * EMBED_D + d] = r[j] * sinv[j];
}

// ---------------- fused kernel: 2 classes per block, shared label scan ----------
__global__ void __launch_bounds__(1024, 1)
k_main(const float* __restrict__ tokens,
       const void*  __restrict__ labels_raw,
       const float* __restrict__ protos,
       float* __restrict__ out) {
    extern __shared__ __align__(16) char dyn[];

    int tid  = threadIdx.x;
    int half = tid >> 9;
    int ltid = tid & 511;
    int wid  = ltid >> 5, lane = ltid & 31;
    int fw   = tid >> 5;                       // full-block warp id 0..31
    int c0   = blockIdx.x * 2, c1 = c0 + 1;
    int c    = c0 + half;

    char* hb  = dyn + half * HALF_BYTES;
    float*    sp    = (float*)(hb + OFF_SP);
    float*    ssS   = (float*)(hb + OFF_SSS);
    float*    ssV   = (float*)(hb + OFF_SSV);
    float*    ssI   = (float*)(hb + OFF_SSI);
    int*      sidx  = (int*)  (hb + OFF_SIDX);
    unsigned* cmask = (unsigned*)(hb + OFF_CMASK);
    int*      cpre  = (int*)  (hb + OFF_CPRE);
    int*      wsum  = (int*)  (hb + OFF_WSUM);
    float*    su    = (float*)(hb + OFF_SU);
    float*    red   = (float*)(hb + OFF_RED);
    float*    sinv  = (float*)(hb + OFF_SINV);
    int*      s_n   = (int*)  (hb + OFF_SN);
    int*      s_lt  = s_n + 1;
    unsigned* cm0   = (unsigned*)(dyn + OFF_CMASK);
    unsigned* cm1   = (unsigned*)(dyn + HALF_BYTES + OFF_CMASK);

    // stage this half's prototypes (DRAM loads in flight during label scan)
    {
        const float4* pg = (const float4*)(protos + (size_t)c * NUM_PROTO * EMBED_D);
        float4* ps = (float4*)sp;
        for (int i = ltid; i < NUM_PROTO * EMBED_D / 4; i += 512) ps[i] = pg[i];
    }
    if (ltid == 0) *s_lt = 0;

    // per-warp label dtype detection (uniform branch, hoisted out of load loops)
    const long long* l64 = (const long long*)labels_raw;
    bool is64;
    {
        long long v = l64[lane];
        unsigned bal = __ballot_sync(FULLM, v >= 0 && v < NUM_CLASSES);
        is64 = (__popc(bal) >= 16);
    }
    __syncthreads();   // s_lt init visible block-wide before shared scan

    // --- shared pass 1: all 32 warps scan labels ONCE, masks for both classes ---
    const int4* l4 = (const int4*)labels_raw;
    if (!is64) {
        #pragma unroll
        for (int k = 0; k < 2; k++) {            // 2 int4 per thread = 8192 labels
            int4 v = l4[tid + 1024 * k];
            unsigned a0 = __ballot_sync(FULLM, v.x == c0);
            unsigned a1 = __ballot_sync(FULLM, v.y == c0);
            unsigned a2 = __ballot_sync(FULLM, v.z == c0);
            unsigned a3 = __ballot_sync(FULLM, v.w == c0);
            unsigned b0 = __ballot_sync(FULLM, v.x == c1);
            unsigned b1 = __ballot_sync(FULLM, v.y == c1);
            unsigned b2 = __ballot_sync(FULLM, v.z == c1);
            unsigned b3 = __ballot_sync(FULLM, v.w == c1);
            if ((tid & 31) == 0) {
                int mb = (k * 32 + fw) * 4;
                cm0[mb] = a0; cm0[mb+1] = a1; cm0[mb+2] = a2; cm0[mb+3] = a3;
                cm1[mb] = b0; cm1[mb+1] = b1; cm1[mb+2] = b2; cm1[mb+3] = b3;
            }
        }
    } else {
        #pragma unroll
        for (int k = 0; k < 4; k++) {            // int4 = 2 int64 labels (.x, .z)
            int4 v = l4[tid + 1024 * k];
            unsigned a0 = __ballot_sync(FULLM, v.x == c0);
            unsigned a1 = __ballot_sync(FULLM, v.z == c0);
            unsigned b0 = __ballot_sync(FULLM, v.x == c1);
            unsigned b1 = __ballot_sync(FULLM, v.z == c1);
            if ((tid & 31) == 0) {
                int mb = (k * 32 + fw) * 2;
                cm0[mb] = a0; cm0[mb+1] = a1;
                cm1[mb] = b0; cm1[mb+1] = b1;
            }
        }
    }
    __syncthreads();   // masks visible; halves independent from here on

    // --- two-level exclusive prefix over 256 mask popcounts (per half) ---
    if (wid < 8) {
        int v = __popc(cmask[wid * 32 + lane]);
        int inc = v;
        #pragma unroll
        for (int o = 1; o < 32; o <<= 1) {
            int t = __shfl_up_sync(FULLM, inc, o);
            if (lane >= o) inc += t;
        }
        cpre[wid * 32 + lane] = inc - v;
        if (lane == 31) wsum[wid] = inc;
    }
    HBAR(half);
    if (wid == 0 && lane < 8) {
        int v = wsum[lane];
        int inc = v;
        #pragma unroll
        for (int o = 1; o < 8; o <<= 1) {
            int t = __shfl_up_sync(0xffu, inc, o);
            if (lane >= o) inc += t;
        }
        wsum[lane] = inc - v;
        if (lane == 7) *s_n = inc;
    }
    HBAR(half);

    int n_c = *s_n;
    if (n_c == 0) {   // out = l2norm(0.98*proto) = proto (unit-norm input)
        #pragma unroll
        for (int j = 0; j < NUM_PROTO; j++)
            out[(size_t)(c * NUM_PROTO + j) * EMBED_D + ltid] = sp[j * EMBED_D + ltid];
        return;
    }
    bool sm = (n_c <= NCAP);

    // --- lazy fallback offset: only when n_c > NCAP (statistically unreachable) ---
    if (!sm) {
        int cnt = 0;
        for (int t = ltid; t < NQ; t += 512) {
            int lab = is64 ? (int)l64[t] : ((const int*)labels_raw)[t];
            if (lab < c) cnt++;
        }
        cnt = (int)warp_sum((float)cnt);          // exact for counts <= 2^24
        if (lane == 0 && cnt) atomicAdd(s_lt, cnt);
        HBAR(half);
    }
    int  off = *s_lt;
    int* dst = sm ? sidx : (g_fidx + off);

    // --- pass 2: replay cached masks; thread per sub-chunk, no label reloads ---
    if (ltid < 256) {
        unsigned m = cmask[ltid];
        if (m) {
            int pos = wsum[ltid >> 5] + cpre[ltid];
            int base;
            int mult = is64 ? 2 : 4;
            if (!is64) {
                int k = ltid >> 7, w = (ltid >> 2) & 31, cc = ltid & 3;
                base = 4 * (32 * w + 1024 * k) + cc;
            } else {
                int k = ltid >> 6, w = (ltid >> 1) & 31, cc = ltid & 1;
                base = 2 * (32 * w + 1024 * k) + cc;
            }
            while (m) {
                int l = __ffs(m) - 1; m &= m - 1;
                dst[pos++] = base + mult * l;
            }
        }
    }
    HBAR(half);

    if (sm) {
        class_body<true >(c, n_c, half, ltid, tokens, out, sp, sidx,
                          ssS, ssV, ssI, su, red, sinv);
    } else {  // statistically unreachable; correct fallback via global scratch
        class_body<false>(c, n_c, half, ltid, tokens, out, sp, g_fidx + off,
                          g_Sf + (size_t)off * SROW, g_vf + off, g_if + off,
                          su, red, sinv);
    }
}

// -------------------------------- launch ---------------------------------------
extern "C" void kernel_launch(void* const* d_in, const int* in_sizes, int n_in,
                              void* d_out, int out_size) {
    const float* tokens = (const float*)d_in[0];
    const void*  labels = d_in[1];
    const float* protos = (const float*)d_in[2];
    float* out = (float*)d_out;

    cudaFuncSetAttribute(k_main, cudaFuncAttributeMaxDynamicSharedMemorySize,
                         SMEM_TOTAL);
    k_main<<<NUM_CLASSES / 2, 1024, SMEM_TOTAL>>>(tokens, labels, protos, out);
}